// round 2
// baseline (speedup 1.0000x reference)
#include <cuda_runtime.h>
#include <math.h>

// ---------------------------------------------------------------------------
// ExtractorLoss: -mean(10*log10(term1/term2)) where term1/term2 are masked
// means of PSD(x, f) over a 201-bin frequency grid. PSD = GEMM of x against
// a DFT basis. Pipeline:
//   K1 basis_kernel : build interleaved [cos;sin] basis  (device scalars read on GPU)
//   K2 gemm_kernel  : X[B,T] x basis[448,T] -> psd[B,224]  (f32x2 packed FMA)
//   K3 snr_kernel   : per-row masked reductions -> snr[B]
//   K4 mean_kernel  : -mean(snr) -> d_out[0]
// ---------------------------------------------------------------------------

#define T_MAX 3616
#define GMAX  224            // capacity of frequency bins (actual: 201)
#define NCOL  (2 * GMAX)     // 448 interleaved cos/sin columns (zero-padded)
#define BMAX  4096

#define BM 64
#define BN 64
#define BK 8
#define APAD 68              // smem row pad (conflict-free STS, 16B-aligned rows)

__device__ float g_basis[NCOL * T_MAX];   // [col][t], col 2g=cos_g, 2g+1=sin_g
__device__ float g_psd[BMAX * GMAX];
__device__ float g_snr[BMAX];

// ---- f32x2 packed helpers (sm_100a+) --------------------------------------
__device__ __forceinline__ unsigned long long pack2(float lo, float hi) {
    unsigned long long r;
    asm("mov.b64 %0, {%1, %2};" : "=l"(r) : "f"(lo), "f"(hi));
    return r;
}
__device__ __forceinline__ void unpack2(unsigned long long v, float& lo, float& hi) {
    asm("mov.b64 {%0, %1}, %2;" : "=f"(lo), "=f"(hi) : "l"(v));
}
__device__ __forceinline__ void fma2(unsigned long long& d,
                                     unsigned long long a, unsigned long long b) {
    asm("fma.rn.f32x2 %0, %1, %2, %0;" : "+l"(d) : "l"(a), "l"(b));
}

// ---------------------------------------------------------------------------
// K1: basis. Replicates the reference's fp32 phase rounding:
//   ph = fl32( fl32( fl32(2*pi/fs) * fl32(f_bpm/60) ) * t )
// then reduces that fp32 value exactly (double) to [-pi, pi] before fp32 trig,
// so the result matches JAX's correctly-rounded f32 cos/sin to ~1 ulp even
// under --use_fast_math.
// ---------------------------------------------------------------------------
__global__ void basis_kernel(const int* __restrict__ fs_p,
                             const int* __restrict__ samp_p,
                             const int* __restrict__ fmin_p,
                             const int* __restrict__ fmax_p,
                             int T) {
    int idx = blockIdx.x * blockDim.x + threadIdx.x;
    if (idx >= NCOL * T) return;
    int c = idx / T;
    int t = idx - c * T;

    int fs = *fs_p, samp = *samp_p, fmin = *fmin_p, fmax = *fmax_p;
    int ngrid = (fmax - fmin) / samp + 1;

    float v = 0.0f;
    if (c < 2 * ngrid) {
        int g = c >> 1;
        float fHz = (float)(fmin + g * samp) / 60.0f;
        float s   = (float)(6.283185307179586 / (double)fs);
        float ph  = (s * fHz) * (float)t;                 // JAX fp32 rounding order
        double dph = (double)ph;
        double r = dph - floor(dph * 0.15915494309189535) * 6.283185307179586;
        if (r > 3.141592653589793) r -= 6.283185307179586;
        float rf = (float)r;
        v = (c & 1) ? sinf(rf) : cosf(rf);
    }
    g_basis[(size_t)c * T + t] = v;
}

// ---------------------------------------------------------------------------
// K2: GEMM.  C[B, 448] = X[B,T] * basisT, fused into psd = a^2 + b^2.
// 64x64 tile, BK=8, 64 threads, 8x8 micro-tile on f32x2 pairs.
// Assumes T % 8 == 0 and 16B-aligned rows (T % 4 == 0); holds for T=3600.
// ---------------------------------------------------------------------------
__global__ __launch_bounds__(64) void gemm_kernel(const float* __restrict__ x,
                                                  int B, int T) {
    __shared__ __align__(16) float As[2][BK][APAD];
    __shared__ __align__(16) float Bs[2][BK][APAD];

    const int t  = threadIdx.x;                  // 0..63
    // lane mapping: quarter-warp = 4 tx x 2 ty -> broadcast A, conflict-free B
    const int tx = (t & 3) | ((t & 32) >> 3);    // 0..7 (n position)
    const int ty = (t >> 2) & 7;                 // 0..7 (m position)
    const int rowBase = blockIdx.x * BM;
    const int colBase = blockIdx.y * BN;
    const int kIters  = (T + BK - 1) / BK;

    unsigned long long acc[8][4];
#pragma unroll
    for (int m = 0; m < 8; m++)
#pragma unroll
        for (int j = 0; j < 4; j++) acc[m][j] = 0ull;

    // tile-load mapping: thread -> rows r0, r0+32 at k-group kg (4 floats each)
    const int r0 = t >> 1;
    const int kg = (t & 1) * 4;

    float4 av0, av1, bv0, bv1;

    auto loadTiles = [&](int it) {
        const int k0 = it * BK + kg;
        av0 = make_float4(0.f, 0.f, 0.f, 0.f);
        av1 = av0; bv0 = av0; bv1 = av0;
        if (k0 < T) {
            int gr0 = rowBase + r0;
            int gr1 = rowBase + r0 + 32;
            if (gr0 < B) av0 = *(const float4*)(x + (size_t)gr0 * T + k0);
            if (gr1 < B) av1 = *(const float4*)(x + (size_t)gr1 * T + k0);
            bv0 = *(const float4*)(g_basis + (size_t)(colBase + r0)      * T + k0);
            bv1 = *(const float4*)(g_basis + (size_t)(colBase + r0 + 32) * T + k0);
        }
    };
    auto storeTiles = [&](int buf) {
#pragma unroll
        for (int c = 0; c < 4; c++) {
            As[buf][kg + c][r0]      = (&av0.x)[c];
            As[buf][kg + c][r0 + 32] = (&av1.x)[c];
            Bs[buf][kg + c][r0]      = (&bv0.x)[c];
            Bs[buf][kg + c][r0 + 32] = (&bv1.x)[c];
        }
    };
    auto computeTile = [&](int buf) {
#pragma unroll
        for (int kk = 0; kk < BK; kk++) {
            float4 a0 = *(const float4*)&As[buf][kk][ty * 8];
            float4 a1 = *(const float4*)&As[buf][kk][ty * 8 + 4];
            float4 b0 = *(const float4*)&Bs[buf][kk][tx * 8];
            float4 b1 = *(const float4*)&Bs[buf][kk][tx * 8 + 4];
            unsigned long long bp0 = pack2(b0.x, b0.y);
            unsigned long long bp1 = pack2(b0.z, b0.w);
            unsigned long long bp2 = pack2(b1.x, b1.y);
            unsigned long long bp3 = pack2(b1.z, b1.w);
            float am[8] = {a0.x, a0.y, a0.z, a0.w, a1.x, a1.y, a1.z, a1.w};
#pragma unroll
            for (int m = 0; m < 8; m++) {
                unsigned long long ad = pack2(am[m], am[m]);
                fma2(acc[m][0], ad, bp0);
                fma2(acc[m][1], ad, bp1);
                fma2(acc[m][2], ad, bp2);
                fma2(acc[m][3], ad, bp3);
            }
        }
    };

    loadTiles(0);
    storeTiles(0);
    __syncthreads();

    int buf = 0;
    for (int it = 0; it < kIters; ++it) {
        if (it + 1 < kIters) loadTiles(it + 1);
        computeTile(buf);
        if (it + 1 < kIters) {
            storeTiles(buf ^ 1);
            __syncthreads();
        }
        buf ^= 1;
    }

    // epilogue: psd = cos^2 + sin^2 for the 4 bin-pairs each thread owns
#pragma unroll
    for (int m = 0; m < 8; m++) {
        int row = rowBase + ty * 8 + m;
        if (row < B) {
            float lo, hi;
            float4 p;
            unpack2(acc[m][0], lo, hi); p.x = lo * lo + hi * hi;
            unpack2(acc[m][1], lo, hi); p.y = lo * lo + hi * hi;
            unpack2(acc[m][2], lo, hi); p.z = lo * lo + hi * hi;
            unpack2(acc[m][3], lo, hi); p.w = lo * lo + hi * hi;
            int g0 = (colBase >> 1) + tx * 4;
            *(float4*)(g_psd + (size_t)row * GMAX + g0) = p;
        }
    }
}

// ---------------------------------------------------------------------------
// K3: per-row SNR. One warp per row.
// ---------------------------------------------------------------------------
__global__ void snr_kernel(const int* __restrict__ ftrue,
                           const int* __restrict__ samp_p,
                           const int* __restrict__ delta_p,
                           const int* __restrict__ fmin_p,
                           const int* __restrict__ fmax_p,
                           int B) {
    int row  = blockIdx.x * (blockDim.x >> 5) + (threadIdx.x >> 5);
    int lane = threadIdx.x & 31;
    if (row >= B) return;

    int samp = *samp_p, delta = *delta_p, fmin = *fmin_p, fmax = *fmax_p;
    int ngrid = (fmax - fmin) / samp + 1;
    int f = ftrue[row];

    float tot = 0.f, wan = 0.f;
    for (int g = lane; g < ngrid; g += 32) {
        float p = g_psd[(size_t)row * GMAX + g];
        tot += p;
        int d = fmin + g * samp - f;
        if (d < 0) d = -d;
        if (d <= delta) wan += p;
    }
#pragma unroll
    for (int o = 16; o > 0; o >>= 1) {
        tot += __shfl_xor_sync(0xFFFFFFFFu, tot, o);
        wan += __shfl_xor_sync(0xFFFFFFFFu, wan, o);
    }
    if (lane == 0) {
        int nw = 2 * delta / samp + 1;
        int nu = ngrid - nw;
        float t1 = wan / (float)nw;
        float t2 = (tot - wan) / (float)nu;
        g_snr[row] = 10.0f * log10f(t1 / t2);
    }
}

// ---------------------------------------------------------------------------
// K4: -mean(snr) -> out[0]
// ---------------------------------------------------------------------------
__global__ void mean_kernel(float* __restrict__ out, int B) {
    __shared__ float red[256];
    float s = 0.f;
    for (int i = threadIdx.x; i < B; i += 256) s += g_snr[i];
    red[threadIdx.x] = s;
    __syncthreads();
#pragma unroll
    for (int o = 128; o > 0; o >>= 1) {
        if (threadIdx.x < o) red[threadIdx.x] += red[threadIdx.x + o];
        __syncthreads();
    }
    if (threadIdx.x == 0) out[0] = -(red[0] / (float)B);
}

// ---------------------------------------------------------------------------
extern "C" void kernel_launch(void* const* d_in, const int* in_sizes, int n_in,
                              void* d_out, int out_size) {
    const float* x     = (const float*)d_in[0];
    const int*   ftrue = (const int*)  d_in[1];
    const int*   fs    = (const int*)  d_in[2];
    const int*   delta = (const int*)  d_in[3];
    const int*   samp  = (const int*)  d_in[4];
    const int*   fmin  = (const int*)  d_in[5];
    const int*   fmax  = (const int*)  d_in[6];

    const int B = in_sizes[1];
    const int T = in_sizes[0] / B;

    basis_kernel<<<(NCOL * T + 255) / 256, 256>>>(fs, samp, fmin, fmax, T);

    dim3 grid((B + BM - 1) / BM, NCOL / BN);
    gemm_kernel<<<grid, 64>>>(x, B, T);

    snr_kernel<<<(B + 7) / 8, 256>>>(ftrue, samp, delta, fmin, fmax, B);
    mean_kernel<<<1, 256>>>((float*)d_out, B);
}

// round 6
// speedup vs baseline: 2.3492x; 2.3492x over previous
#include <cuda_runtime.h>
#include <cuda_bf16.h>
#include <math.h>
#include <stdint.h>

// ===========================================================================
// ExtractorLoss via bf16-split legacy-tensor-core GEMM (mma.sync, sm_80 PTX —
// compiles under compute_100; tcgen05 is rejected by this toolchain).
//   K1 convert : x f32 -> (hi,lo) bf16
//   K2 basis   : DFT basis f32 (exact JAX rounding) -> (hi,lo) bf16
//   K3 gemm    : acc = Ah*Bh + Ah*Bl + Al*Bh (fp32), psd=a^2+b^2 in-register
//   K4 snr     : masked means per row, 10*log10       (R2-proven form)
//   K5 mean    : -mean(snr)
// ===========================================================================

#define BMAX   4096
#define TMAXE  3648
#define NCOLS  448          // padded basis rows (2*224); real = 2*ngrid = 402
#define GMAX   224
#define BM     128
#define BN     112
#define KC     64           // K per chunk: 128B rows in smem

__device__ __align__(16) __nv_bfloat16 g_xhi[BMAX * TMAXE];
__device__ __align__(16) __nv_bfloat16 g_xlo[BMAX * TMAXE];
__device__ __align__(16) __nv_bfloat16 g_whi[NCOLS * TMAXE];
__device__ __align__(16) __nv_bfloat16 g_wlo[NCOLS * TMAXE];
__device__ __align__(16) float g_psd[BMAX * GMAX];
__device__ float g_snr[BMAX];

// smem layout per buffer: AH(16K) AL(16K) BH(14K) BL(14K) = 60K; x2 buffers
#define SM_AH 0u
#define SM_AL 16384u
#define SM_BH 32768u
#define SM_BL 47104u
#define BUF_BYTES 61440u
#define SMEM_TOTAL (2u * BUF_BYTES)

// ---------------- PTX helpers ----------------------------------------------
__device__ __forceinline__ uint32_t smem_u32(const void* p) {
    uint32_t a;
    asm("{ .reg .u64 t; cvta.to.shared.u64 t, %1; cvt.u32.u64 %0, t; }"
        : "=r"(a) : "l"(p));
    return a;
}
__device__ __forceinline__ void cp_async16(uint32_t dst, const void* src, int sz) {
    asm volatile("cp.async.cg.shared.global [%0], [%1], 16, %2;"
                 :: "r"(dst), "l"(src), "r"(sz) : "memory");
}
#define CP_COMMIT() asm volatile("cp.async.commit_group;" ::: "memory")
#define CP_WAIT(n)  asm volatile("cp.async.wait_group %0;" :: "n"(n) : "memory")

__device__ __forceinline__ void ldsm4(uint32_t* r, uint32_t a) {
    asm volatile("ldmatrix.sync.aligned.m8n8.x4.shared.b16 {%0,%1,%2,%3}, [%4];"
                 : "=r"(r[0]), "=r"(r[1]), "=r"(r[2]), "=r"(r[3]) : "r"(a));
}
__device__ __forceinline__ void ldsm2(uint32_t* r, uint32_t a) {
    asm volatile("ldmatrix.sync.aligned.m8n8.x2.shared.b16 {%0,%1}, [%2];"
                 : "=r"(r[0]), "=r"(r[1]) : "r"(a));
}
__device__ __forceinline__ void mma_bf16(float* c, const uint32_t* a,
                                         const uint32_t* b) {
    asm volatile(
        "mma.sync.aligned.m16n8k16.row.col.f32.bf16.bf16.f32 "
        "{%0,%1,%2,%3}, {%4,%5,%6,%7}, {%8,%9}, {%0,%1,%2,%3};"
        : "+f"(c[0]), "+f"(c[1]), "+f"(c[2]), "+f"(c[3])
        : "r"(a[0]), "r"(a[1]), "r"(a[2]), "r"(a[3]), "r"(b[0]), "r"(b[1]));
}

// swizzled byte offset of (row r, 16B-chunk kc) in a 128B-row tile
__device__ __forceinline__ uint32_t swz(int r, int kc) {
    return (uint32_t)r * 128u + (uint32_t)((kc ^ (r & 7)) << 4);
}

// ---------------------------------------------------------------------------
// K1: x f32 -> bf16 hi/lo split
// ---------------------------------------------------------------------------
__global__ void convert_kernel(const float* __restrict__ x, int n4) {
    int i = blockIdx.x * blockDim.x + threadIdx.x;
    if (i >= n4) return;
    float4 v = ((const float4*)x)[i];
    float vv[4] = {v.x, v.y, v.z, v.w};
    unsigned short hs[4], ls[4];
#pragma unroll
    for (int j = 0; j < 4; j++) {
        __nv_bfloat16 h = __float2bfloat16(vv[j]);
        float r = vv[j] - __bfloat162float(h);
        hs[j] = __bfloat16_as_ushort(h);
        ls[j] = __bfloat16_as_ushort(__float2bfloat16(r));
    }
    ((uint2*)g_xhi)[i] = make_uint2((uint32_t)hs[0] | ((uint32_t)hs[1] << 16),
                                    (uint32_t)hs[2] | ((uint32_t)hs[3] << 16));
    ((uint2*)g_xlo)[i] = make_uint2((uint32_t)ls[0] | ((uint32_t)ls[1] << 16),
                                    (uint32_t)ls[2] | ((uint32_t)ls[3] << 16));
}

// ---------------------------------------------------------------------------
// K2: basis (JAX fp32 rounding order, exact DP range reduction) -> bf16 hi/lo
// ---------------------------------------------------------------------------
__global__ void basis_kernel(const int* __restrict__ fs_p,
                             const int* __restrict__ samp_p,
                             const int* __restrict__ fmin_p,
                             const int* __restrict__ fmax_p,
                             int T) {
    int idx = blockIdx.x * blockDim.x + threadIdx.x;
    if (idx >= NCOLS * T) return;
    int c = idx / T;
    int t = idx - c * T;

    int fs = *fs_p, samp = *samp_p, fmin = *fmin_p, fmax = *fmax_p;
    int ngrid = (fmax - fmin) / samp + 1;

    float v = 0.0f;
    if (c < 2 * ngrid) {
        int g = c >> 1;
        float fHz = (float)(fmin + g * samp) / 60.0f;
        float s   = (float)(6.283185307179586 / (double)fs);
        float ph  = (s * fHz) * (float)t;            // JAX fp32 rounding order
        double dph = (double)ph;
        double r = dph - floor(dph * 0.15915494309189535) * 6.283185307179586;
        if (r > 3.141592653589793) r -= 6.283185307179586;
        float rf = (float)r;
        v = (c & 1) ? sinf(rf) : cosf(rf);
    }
    __nv_bfloat16 h = __float2bfloat16(v);
    float rlo = v - __bfloat162float(h);
    g_whi[(size_t)c * T + t] = h;
    g_wlo[(size_t)c * T + t] = __float2bfloat16(rlo);
}

// ---------------------------------------------------------------------------
// K3: GEMM via mma.sync. grid (B/128, 448/112); 256 thr = 8 warps (4m x 2n).
// Warp tile 32m x 56n; fragments m16n8k16. psd written directly.
// ---------------------------------------------------------------------------
extern __shared__ __align__(128) uint8_t dynsm[];

__global__ __launch_bounds__(256, 1) void gemm_mma(int Brows, int T, int chunks) {
    const int tid  = threadIdx.x;
    const int lane = tid & 31;
    const int warp = tid >> 5;
    const int wm   = warp & 3;        // 0..3 -> 32-row slice
    const int wn   = warp >> 2;       // 0..1 -> 56-col slice
    const int rowBase = blockIdx.x * BM;
    const int colBase = blockIdx.y * BN;

    const uint32_t smb = smem_u32(dynsm);

    const __nv_bfloat16* Ah = g_xhi + (size_t)rowBase * T;
    const __nv_bfloat16* Al = g_xlo + (size_t)rowBase * T;
    const __nv_bfloat16* Bh = g_whi + (size_t)colBase * T;
    const __nv_bfloat16* Bl = g_wlo + (size_t)colBase * T;

    float acc[2][7][4];
#pragma unroll
    for (int mi = 0; mi < 2; mi++)
#pragma unroll
        for (int j = 0; j < 7; j++)
#pragma unroll
            for (int q = 0; q < 4; q++) acc[mi][j][q] = 0.f;

    // ---- fill one buffer with chunk (cp.async, zfill OOB-K) ----
    auto fill = [&](int buf, int chunk) {
        const int k0 = chunk * KC;
        const uint32_t bb = smb + (uint32_t)buf * BUF_BYTES;
        for (int idx = tid; idx < 3840; idx += 256) {
            const __nv_bfloat16* src;
            uint32_t sec;
            int s = idx, r;
            if (idx < 2048) {
                if (s < 1024) { sec = SM_AH; src = Ah; }
                else          { sec = SM_AL; src = Al; s -= 1024; }
            } else {
                s = idx - 2048;
                if (s < 896)  { sec = SM_BH; src = Bh; }
                else          { sec = SM_BL; src = Bl; s -= 896; }
            }
            r = s >> 3;
            const int c = s & 7;
            const int k = k0 + c * 8;
            cp_async16(bb + sec + swz(r, c), src + (size_t)r * T + k,
                       (k < T) ? 16 : 0);
        }
    };

    // ---- compute one buffered chunk: 4 k16-steps ----
    auto compute = [&](int buf) {
        const uint32_t bb = smb + (uint32_t)buf * BUF_BYTES;
#pragma unroll
        for (int ks = 0; ks < 4; ks++) {
            uint32_t ah[2][4], al[2][4], bh[7][2], bl[7][2];
            // A: lanes 0-7 rows0-7@k0 | 8-15 rows8-15@k0 | 16-23 rows0-7@k8 | 24-31 rows8-15@k8
            {
                const int rA  = wm * 32 + (lane & 15);
                const int kcA = ks * 2 + (lane >> 4);
#pragma unroll
                for (int mi = 0; mi < 2; mi++) {
                    const uint32_t off = swz(rA + mi * 16, kcA);
                    ldsm4(ah[mi], bb + SM_AH + off);
                    ldsm4(al[mi], bb + SM_AL + off);
                }
            }
            // B: x4 per n8-pair: lanes 0-7 n(j)@k0 | 8-15 n(j)@k8 | 16-23 n(j+1)@k0 | 24-31 n(j+1)@k8
            {
                const int rb  = ((lane >> 4) & 1) * 8 + (lane & 7);
                const int kcB = ks * 2 + ((lane >> 3) & 1);
#pragma unroll
                for (int jp = 0; jp < 3; jp++) {
                    const int r = wn * 56 + jp * 16 + rb;
                    const uint32_t off = swz(r, kcB);
                    uint32_t t4[4];
                    ldsm4(t4, bb + SM_BH + off);
                    bh[2 * jp][0] = t4[0]; bh[2 * jp][1] = t4[1];
                    bh[2 * jp + 1][0] = t4[2]; bh[2 * jp + 1][1] = t4[3];
                    ldsm4(t4, bb + SM_BL + off);
                    bl[2 * jp][0] = t4[0]; bl[2 * jp][1] = t4[1];
                    bl[2 * jp + 1][0] = t4[2]; bl[2 * jp + 1][1] = t4[3];
                }
                {   // j=6 via x2 (lanes 0-15 supply addresses)
                    const int r = wn * 56 + 48 + (lane & 7);
                    const int kc2 = ks * 2 + ((lane >> 3) & 1);
                    const uint32_t off = swz(r, kc2);
                    ldsm2(bh[6], bb + SM_BH + off);
                    ldsm2(bl[6], bb + SM_BL + off);
                }
            }
#pragma unroll
            for (int mi = 0; mi < 2; mi++)
#pragma unroll
                for (int j = 0; j < 7; j++) {
                    mma_bf16(acc[mi][j], ah[mi], bh[j]);
                    mma_bf16(acc[mi][j], ah[mi], bl[j]);
                    mma_bf16(acc[mi][j], al[mi], bh[j]);
                }
        }
    };

    // ---- double-buffered mainloop ----
    fill(0, 0);
    CP_COMMIT();
    int buf = 0;
    for (int c = 0; c < chunks; ++c) {
        if (c + 1 < chunks) { fill(buf ^ 1, c + 1); CP_COMMIT(); }
        if (c + 1 < chunks) CP_WAIT(1); else CP_WAIT(0);
        __syncthreads();
        compute(buf);
        __syncthreads();
        buf ^= 1;
    }

    // ---- epilogue: psd = c_even^2 + c_odd^2, write directly ----
    // c0,c1: (row = wm*32+mi*16+lane/4, cols 2q,2q+1) ; c2,c3: row+8
#pragma unroll
    for (int mi = 0; mi < 2; mi++) {
#pragma unroll
        for (int j = 0; j < 7; j++) {
            const int row = rowBase + wm * 32 + mi * 16 + (lane >> 2);
            const int g   = (colBase >> 1) + wn * 28 + j * 4 + (lane & 3);
            const float* cc = acc[mi][j];
            g_psd[(size_t)row * GMAX + g]       = cc[0] * cc[0] + cc[1] * cc[1];
            g_psd[(size_t)(row + 8) * GMAX + g] = cc[2] * cc[2] + cc[3] * cc[3];
        }
    }
}

// ---------------------------------------------------------------------------
// K4: per-row SNR. One warp per row.  (R2-proven form)
// ---------------------------------------------------------------------------
__global__ void snr_kernel(const int* __restrict__ ftrue,
                           const int* __restrict__ samp_p,
                           const int* __restrict__ delta_p,
                           const int* __restrict__ fmin_p,
                           const int* __restrict__ fmax_p,
                           int B) {
    int row  = blockIdx.x * (blockDim.x >> 5) + (threadIdx.x >> 5);
    int lane = threadIdx.x & 31;
    if (row >= B) return;

    int samp = *samp_p, delta = *delta_p, fmin = *fmin_p, fmax = *fmax_p;
    int ngrid = (fmax - fmin) / samp + 1;
    int f = ftrue[row];

    float tot = 0.f, wan = 0.f;
    for (int g = lane; g < ngrid; g += 32) {
        float p = g_psd[(size_t)row * GMAX + g];
        tot += p;
        int d = fmin + g * samp - f;
        if (d < 0) d = -d;
        if (d <= delta) wan += p;
    }
#pragma unroll
    for (int o = 16; o > 0; o >>= 1) {
        tot += __shfl_xor_sync(0xFFFFFFFFu, tot, o);
        wan += __shfl_xor_sync(0xFFFFFFFFu, wan, o);
    }
    if (lane == 0) {
        int nw = 2 * delta / samp + 1;
        int nu = ngrid - nw;
        float t1 = wan / (float)nw;
        float t2 = (tot - wan) / (float)nu;
        g_snr[row] = 10.0f * log10f(t1 / t2);
    }
}

// ---------------------------------------------------------------------------
// K5: -mean(snr)
// ---------------------------------------------------------------------------
__global__ void mean_kernel(float* __restrict__ out, int B) {
    __shared__ float red[256];
    float s = 0.f;
    for (int i = threadIdx.x; i < B; i += 256) s += g_snr[i];
    red[threadIdx.x] = s;
    __syncthreads();
#pragma unroll
    for (int o = 128; o > 0; o >>= 1) {
        if (threadIdx.x < o) red[threadIdx.x] += red[threadIdx.x + o];
        __syncthreads();
    }
    if (threadIdx.x == 0) out[0] = -(red[0] / (float)B);
}

// ---------------------------------------------------------------------------
extern "C" void kernel_launch(void* const* d_in, const int* in_sizes, int n_in,
                              void* d_out, int out_size) {
    const float* x     = (const float*)d_in[0];
    const int*   ftrue = (const int*)  d_in[1];
    const int*   fs    = (const int*)  d_in[2];
    const int*   delta = (const int*)  d_in[3];
    const int*   samp  = (const int*)  d_in[4];
    const int*   fmin  = (const int*)  d_in[5];
    const int*   fmax  = (const int*)  d_in[6];

    const int B = in_sizes[1];
    const int T = in_sizes[0] / B;

    const int n4 = (B * T) / 4;
    convert_kernel<<<(n4 + 255) / 256, 256>>>(x, n4);
    basis_kernel<<<(NCOLS * T + 255) / 256, 256>>>(fs, samp, fmin, fmax, T);

    cudaFuncSetAttribute(gemm_mma, cudaFuncAttributeMaxDynamicSharedMemorySize,
                         SMEM_TOTAL);
    const int chunks = (T + KC - 1) / KC;   // 57 for T=3600 (tail zfilled)
    gemm_mma<<<dim3(B / BM, NCOLS / BN), 256, SMEM_TOTAL>>>(B, T, chunks);

    snr_kernel<<<(B + 7) / 8, 256>>>(ftrue, samp, delta, fmin, fmax, B);
    mean_kernel<<<1, 256>>>((float*)d_out, B);
}

// round 7
// speedup vs baseline: 2.4589x; 1.0467x over previous
#include <cuda_runtime.h>
#include <cuda_bf16.h>
#include <math.h>
#include <stdint.h>

// ===========================================================================
// ExtractorLoss via bf16-split legacy-tensor-core GEMM (mma.sync, sm_80 PTX).
//   K1 prep  : fused [x f32 -> (hi,lo) bf16] + [DFT basis -> (hi,lo) bf16]
//   K2 gemm  : acc = Ah*Bh + Ah*Bl + Al*Bh (fp32), psd=a^2+b^2 in-register
//              512 threads / CTA (16 warps = 8m x 2n) for latency hiding
//   K3 snr   : masked means per row, 10*log10
//   K4 mean  : -mean(snr)
// ===========================================================================

#define BMAX   4096
#define TMAXE  3648
#define NCOLS  448          // padded basis rows (2*224); real = 2*ngrid = 402
#define GMAX   224
#define BM     128
#define BN     112
#define KC     64           // K per chunk: 128B rows in smem

__device__ __align__(16) __nv_bfloat16 g_xhi[BMAX * TMAXE];
__device__ __align__(16) __nv_bfloat16 g_xlo[BMAX * TMAXE];
__device__ __align__(16) __nv_bfloat16 g_whi[NCOLS * TMAXE];
__device__ __align__(16) __nv_bfloat16 g_wlo[NCOLS * TMAXE];
__device__ __align__(16) float g_psd[BMAX * GMAX];
__device__ float g_snr[BMAX];

// smem layout per buffer: AH(16K) AL(16K) BH(14K) BL(14K) = 60K; x2 buffers
#define SM_AH 0u
#define SM_AL 16384u
#define SM_BH 32768u
#define SM_BL 47104u
#define BUF_BYTES 61440u
#define SMEM_TOTAL (2u * BUF_BYTES)

// ---------------- PTX helpers ----------------------------------------------
__device__ __forceinline__ uint32_t smem_u32(const void* p) {
    uint32_t a;
    asm("{ .reg .u64 t; cvta.to.shared.u64 t, %1; cvt.u32.u64 %0, t; }"
        : "=r"(a) : "l"(p));
    return a;
}
__device__ __forceinline__ void cp_async16(uint32_t dst, const void* src, int sz) {
    asm volatile("cp.async.cg.shared.global [%0], [%1], 16, %2;"
                 :: "r"(dst), "l"(src), "r"(sz) : "memory");
}
#define CP_COMMIT() asm volatile("cp.async.commit_group;" ::: "memory")
#define CP_WAIT(n)  asm volatile("cp.async.wait_group %0;" :: "n"(n) : "memory")

__device__ __forceinline__ void ldsm4(uint32_t* r, uint32_t a) {
    asm volatile("ldmatrix.sync.aligned.m8n8.x4.shared.b16 {%0,%1,%2,%3}, [%4];"
                 : "=r"(r[0]), "=r"(r[1]), "=r"(r[2]), "=r"(r[3]) : "r"(a));
}
__device__ __forceinline__ void ldsm2(uint32_t* r, uint32_t a) {
    asm volatile("ldmatrix.sync.aligned.m8n8.x2.shared.b16 {%0,%1}, [%2];"
                 : "=r"(r[0]), "=r"(r[1]) : "r"(a));
}
__device__ __forceinline__ void mma_bf16(float* c, const uint32_t* a,
                                         const uint32_t* b) {
    asm volatile(
        "mma.sync.aligned.m16n8k16.row.col.f32.bf16.bf16.f32 "
        "{%0,%1,%2,%3}, {%4,%5,%6,%7}, {%8,%9}, {%0,%1,%2,%3};"
        : "+f"(c[0]), "+f"(c[1]), "+f"(c[2]), "+f"(c[3])
        : "r"(a[0]), "r"(a[1]), "r"(a[2]), "r"(a[3]), "r"(b[0]), "r"(b[1]));
}

// swizzled byte offset of (row r, 16B-chunk kc) in a 128B-row tile
__device__ __forceinline__ uint32_t swz(int r, int kc) {
    return (uint32_t)r * 128u + (uint32_t)((kc ^ (r & 7)) << 4);
}

// ---------------------------------------------------------------------------
// K1: fused prep. idx < n4: x f32->bf16 hi/lo (float4 granularity).
//     idx >= n4: basis element (JAX fp32 rounding, exact DP range reduction).
// ---------------------------------------------------------------------------
__global__ void prep_kernel(const float* __restrict__ x,
                            const int* __restrict__ fs_p,
                            const int* __restrict__ samp_p,
                            const int* __restrict__ fmin_p,
                            const int* __restrict__ fmax_p,
                            int T, int n4, int nbasis) {
    int idx = blockIdx.x * blockDim.x + threadIdx.x;
    if (idx < n4) {
        float4 v = ((const float4*)x)[idx];
        float vv[4] = {v.x, v.y, v.z, v.w};
        unsigned short hs[4], ls[4];
#pragma unroll
        for (int j = 0; j < 4; j++) {
            __nv_bfloat16 h = __float2bfloat16(vv[j]);
            float r = vv[j] - __bfloat162float(h);
            hs[j] = __bfloat16_as_ushort(h);
            ls[j] = __bfloat16_as_ushort(__float2bfloat16(r));
        }
        ((uint2*)g_xhi)[idx] = make_uint2((uint32_t)hs[0] | ((uint32_t)hs[1] << 16),
                                          (uint32_t)hs[2] | ((uint32_t)hs[3] << 16));
        ((uint2*)g_xlo)[idx] = make_uint2((uint32_t)ls[0] | ((uint32_t)ls[1] << 16),
                                          (uint32_t)ls[2] | ((uint32_t)ls[3] << 16));
        return;
    }
    int bi = idx - n4;
    if (bi >= nbasis) return;
    int c = bi / T;
    int t = bi - c * T;

    int fs = *fs_p, samp = *samp_p, fmin = *fmin_p, fmax = *fmax_p;
    int ngrid = (fmax - fmin) / samp + 1;

    float v = 0.0f;
    if (c < 2 * ngrid) {
        int g = c >> 1;
        float fHz = (float)(fmin + g * samp) / 60.0f;
        float s   = (float)(6.283185307179586 / (double)fs);
        float ph  = (s * fHz) * (float)t;            // JAX fp32 rounding order
        double dph = (double)ph;
        double r = dph - floor(dph * 0.15915494309189535) * 6.283185307179586;
        if (r > 3.141592653589793) r -= 6.283185307179586;
        float rf = (float)r;
        v = (c & 1) ? sinf(rf) : cosf(rf);
    }
    __nv_bfloat16 h = __float2bfloat16(v);
    float rlo = v - __bfloat162float(h);
    g_whi[(size_t)c * T + t] = h;
    g_wlo[(size_t)c * T + t] = __float2bfloat16(rlo);
}

// ---------------------------------------------------------------------------
// K2: GEMM via mma.sync. grid (B/128, 448/112); 512 thr = 16 warps (8m x 2n).
// Warp tile 16m x 56n; fragments m16n8k16. psd written directly.
// ---------------------------------------------------------------------------
extern __shared__ __align__(128) uint8_t dynsm[];

__global__ __launch_bounds__(512, 1) void gemm_mma(int Brows, int T, int chunks) {
    const int tid  = threadIdx.x;
    const int lane = tid & 31;
    const int warp = tid >> 5;
    const int wm   = warp & 7;        // 0..7 -> 16-row slice
    const int wn   = warp >> 3;       // 0..1 -> 56-col slice
    const int rowBase = blockIdx.x * BM;
    const int colBase = blockIdx.y * BN;

    const uint32_t smb = smem_u32(dynsm);

    const __nv_bfloat16* Ah = g_xhi + (size_t)rowBase * T;
    const __nv_bfloat16* Al = g_xlo + (size_t)rowBase * T;
    const __nv_bfloat16* Bh = g_whi + (size_t)colBase * T;
    const __nv_bfloat16* Bl = g_wlo + (size_t)colBase * T;

    float acc[7][4];
#pragma unroll
    for (int j = 0; j < 7; j++)
#pragma unroll
        for (int q = 0; q < 4; q++) acc[j][q] = 0.f;

    // ---- fill one buffer with chunk (cp.async, zfill OOB-K) ----
    auto fill = [&](int buf, int chunk) {
        const int k0 = chunk * KC;
        const uint32_t bb = smb + (uint32_t)buf * BUF_BYTES;
        for (int idx = tid; idx < 3840; idx += 512) {
            const __nv_bfloat16* src;
            uint32_t sec;
            int s = idx, r;
            if (idx < 2048) {
                if (s < 1024) { sec = SM_AH; src = Ah; }
                else          { sec = SM_AL; src = Al; s -= 1024; }
            } else {
                s = idx - 2048;
                if (s < 896)  { sec = SM_BH; src = Bh; }
                else          { sec = SM_BL; src = Bl; s -= 896; }
            }
            r = s >> 3;
            const int c = s & 7;
            const int k = k0 + c * 8;
            cp_async16(bb + sec + swz(r, c), src + (size_t)r * T + k,
                       (k < T) ? 16 : 0);
        }
    };

    // ---- compute one buffered chunk: 4 k16-steps ----
    auto compute = [&](int buf) {
        const uint32_t bb = smb + (uint32_t)buf * BUF_BYTES;
#pragma unroll
        for (int ks = 0; ks < 4; ks++) {
            uint32_t ah[4], al[4], bh[7][2], bl[7][2];
            // A: lanes 0-7 rows0-7@k0 | 8-15 rows8-15@k0 | 16-23 rows0-7@k8 | 24-31 rows8-15@k8
            {
                const int rA  = wm * 16 + (lane & 15);
                const int kcA = ks * 2 + (lane >> 4);
                const uint32_t off = swz(rA, kcA);
                ldsm4(ah, bb + SM_AH + off);
                ldsm4(al, bb + SM_AL + off);
            }
            // B: x4 per n8-pair: lanes 0-7 n(j)@k0 | 8-15 n(j)@k8 | 16-23 n(j+1)@k0 | 24-31 n(j+1)@k8
            {
                const int rb  = ((lane >> 4) & 1) * 8 + (lane & 7);
                const int kcB = ks * 2 + ((lane >> 3) & 1);
#pragma unroll
                for (int jp = 0; jp < 3; jp++) {
                    const int r = wn * 56 + jp * 16 + rb;
                    const uint32_t off = swz(r, kcB);
                    uint32_t t4[4];
                    ldsm4(t4, bb + SM_BH + off);
                    bh[2 * jp][0] = t4[0]; bh[2 * jp][1] = t4[1];
                    bh[2 * jp + 1][0] = t4[2]; bh[2 * jp + 1][1] = t4[3];
                    ldsm4(t4, bb + SM_BL + off);
                    bl[2 * jp][0] = t4[0]; bl[2 * jp][1] = t4[1];
                    bl[2 * jp + 1][0] = t4[2]; bl[2 * jp + 1][1] = t4[3];
                }
                {   // j=6 via x2 (lanes 0-15 supply addresses)
                    const int r = wn * 56 + 48 + (lane & 7);
                    const int kc2 = ks * 2 + ((lane >> 3) & 1);
                    const uint32_t off = swz(r, kc2);
                    ldsm2(bh[6], bb + SM_BH + off);
                    ldsm2(bl[6], bb + SM_BL + off);
                }
            }
#pragma unroll
            for (int j = 0; j < 7; j++) {
                mma_bf16(acc[j], ah, bh[j]);
                mma_bf16(acc[j], ah, bl[j]);
                mma_bf16(acc[j], al, bh[j]);
            }
        }
    };

    // ---- double-buffered mainloop ----
    fill(0, 0);
    CP_COMMIT();
    int buf = 0;
    for (int c = 0; c < chunks; ++c) {
        if (c + 1 < chunks) { fill(buf ^ 1, c + 1); CP_COMMIT(); }
        if (c + 1 < chunks) CP_WAIT(1); else CP_WAIT(0);
        __syncthreads();
        compute(buf);
        __syncthreads();
        buf ^= 1;
    }

    // ---- epilogue: psd = c_even^2 + c_odd^2, write directly ----
#pragma unroll
    for (int j = 0; j < 7; j++) {
        const int row = rowBase + wm * 16 + (lane >> 2);
        const int g   = (colBase >> 1) + wn * 28 + j * 4 + (lane & 3);
        const float* cc = acc[j];
        g_psd[(size_t)row * GMAX + g]       = cc[0] * cc[0] + cc[1] * cc[1];
        g_psd[(size_t)(row + 8) * GMAX + g] = cc[2] * cc[2] + cc[3] * cc[3];
    }
}

// ---------------------------------------------------------------------------
// K3: per-row SNR. One warp per row.
// ---------------------------------------------------------------------------
__global__ void snr_kernel(const int* __restrict__ ftrue,
                           const int* __restrict__ samp_p,
                           const int* __restrict__ delta_p,
                           const int* __restrict__ fmin_p,
                           const int* __restrict__ fmax_p,
                           int B) {
    int row  = blockIdx.x * (blockDim.x >> 5) + (threadIdx.x >> 5);
    int lane = threadIdx.x & 31;
    if (row >= B) return;

    int samp = *samp_p, delta = *delta_p, fmin = *fmin_p, fmax = *fmax_p;
    int ngrid = (fmax - fmin) / samp + 1;
    int f = ftrue[row];

    float tot = 0.f, wan = 0.f;
    for (int g = lane; g < ngrid; g += 32) {
        float p = g_psd[(size_t)row * GMAX + g];
        tot += p;
        int d = fmin + g * samp - f;
        if (d < 0) d = -d;
        if (d <= delta) wan += p;
    }
#pragma unroll
    for (int o = 16; o > 0; o >>= 1) {
        tot += __shfl_xor_sync(0xFFFFFFFFu, tot, o);
        wan += __shfl_xor_sync(0xFFFFFFFFu, wan, o);
    }
    if (lane == 0) {
        int nw = 2 * delta / samp + 1;
        int nu = ngrid - nw;
        float t1 = wan / (float)nw;
        float t2 = (tot - wan) / (float)nu;
        g_snr[row] = 10.0f * log10f(t1 / t2);
    }
}

// ---------------------------------------------------------------------------
// K4: -mean(snr), 1024 threads + shuffle reduction
// ---------------------------------------------------------------------------
__global__ void mean_kernel(float* __restrict__ out, int B) {
    __shared__ float red[32];
    const int tid = threadIdx.x, lane = tid & 31, wid = tid >> 5;
    float s = 0.f;
    for (int i = tid; i < B; i += 1024) s += g_snr[i];
#pragma unroll
    for (int o = 16; o > 0; o >>= 1) s += __shfl_xor_sync(0xFFFFFFFFu, s, o);
    if (lane == 0) red[wid] = s;
    __syncthreads();
    if (wid == 0) {
        s = red[lane];
#pragma unroll
        for (int o = 16; o > 0; o >>= 1) s += __shfl_xor_sync(0xFFFFFFFFu, s, o);
        if (lane == 0) out[0] = -(s / (float)B);
    }
}

// ---------------------------------------------------------------------------
extern "C" void kernel_launch(void* const* d_in, const int* in_sizes, int n_in,
                              void* d_out, int out_size) {
    const float* x     = (const float*)d_in[0];
    const int*   ftrue = (const int*)  d_in[1];
    const int*   fs    = (const int*)  d_in[2];
    const int*   delta = (const int*)  d_in[3];
    const int*   samp  = (const int*)  d_in[4];
    const int*   fmin  = (const int*)  d_in[5];
    const int*   fmax  = (const int*)  d_in[6];

    const int B = in_sizes[1];
    const int T = in_sizes[0] / B;

    const int n4 = (B * T) / 4;
    const int nbasis = NCOLS * T;
    prep_kernel<<<(n4 + nbasis + 255) / 256, 256>>>(x, fs, samp, fmin, fmax,
                                                    T, n4, nbasis);

    cudaFuncSetAttribute(gemm_mma, cudaFuncAttributeMaxDynamicSharedMemorySize,
                         SMEM_TOTAL);
    const int chunks = (T + KC - 1) / KC;   // 57 for T=3600 (tail zfilled)
    gemm_mma<<<dim3(B / BM, NCOLS / BN), 512, SMEM_TOTAL>>>(B, T, chunks);

    snr_kernel<<<(B + 7) / 8, 256>>>(ftrue, samp, delta, fmin, fmax, B);
    mean_kernel<<<1, 1024>>>((float*)d_out, B);
}

// round 8
// speedup vs baseline: 3.8876x; 1.5810x over previous
#include <cuda_runtime.h>
#include <cuda_bf16.h>
#include <math.h>
#include <stdint.h>

// ===========================================================================
// ExtractorLoss via bf16-split legacy-tensor-core GEMM (mma.sync, sm_80 PTX)
// with DFT periodicity K-folding:
//   For integer bpm grid, W[g, t + 60*fs] == W[g, t]  (phase shift = 2*pi*f).
//   T = 3600 = 2 * (60*fs=1800)  =>  fold x_t + x_{t+1800}, K halves.
//   K1 prep  : fold x (fp32) -> (hi,lo) bf16 ; basis over t < Tf -> bf16
//   K2 gemm  : acc = Ah*Bh + Ah*Bl + Al*Bh (fp32), psd=a^2+b^2 in-register
//   K3 snr   : masked means per row, 10*log10
//   K4 mean  : -mean(snr)
// ===========================================================================

#define BMAX   4096
#define TMAXE  3648
#define NCOLS  448          // padded basis rows (2*224); real = 2*ngrid = 402
#define GMAX   224
#define BM     128
#define BN     112
#define KC     64           // K per chunk: 128B rows in smem

__device__ __align__(16) __nv_bfloat16 g_xhi[BMAX * TMAXE];
__device__ __align__(16) __nv_bfloat16 g_xlo[BMAX * TMAXE];
__device__ __align__(16) __nv_bfloat16 g_whi[NCOLS * TMAXE];
__device__ __align__(16) __nv_bfloat16 g_wlo[NCOLS * TMAXE];
__device__ __align__(16) float g_psd[BMAX * GMAX];
__device__ float g_snr[BMAX];
__device__ int   g_Tf;      // folded K, written by prep, read by gemm

// smem layout per buffer: AH(16K) AL(16K) BH(14K) BL(14K) = 60K; x2 buffers
#define SM_AH 0u
#define SM_AL 16384u
#define SM_BH 32768u
#define SM_BL 47104u
#define BUF_BYTES 61440u
#define SMEM_TOTAL (2u * BUF_BYTES)

// ---------------- PTX helpers ----------------------------------------------
__device__ __forceinline__ uint32_t smem_u32(const void* p) {
    uint32_t a;
    asm("{ .reg .u64 t; cvta.to.shared.u64 t, %1; cvt.u32.u64 %0, t; }"
        : "=r"(a) : "l"(p));
    return a;
}
__device__ __forceinline__ void cp_async16(uint32_t dst, const void* src, int sz) {
    asm volatile("cp.async.cg.shared.global [%0], [%1], 16, %2;"
                 :: "r"(dst), "l"(src), "r"(sz) : "memory");
}
#define CP_COMMIT() asm volatile("cp.async.commit_group;" ::: "memory")
#define CP_WAIT(n)  asm volatile("cp.async.wait_group %0;" :: "n"(n) : "memory")

__device__ __forceinline__ void ldsm4(uint32_t* r, uint32_t a) {
    asm volatile("ldmatrix.sync.aligned.m8n8.x4.shared.b16 {%0,%1,%2,%3}, [%4];"
                 : "=r"(r[0]), "=r"(r[1]), "=r"(r[2]), "=r"(r[3]) : "r"(a));
}
__device__ __forceinline__ void ldsm2(uint32_t* r, uint32_t a) {
    asm volatile("ldmatrix.sync.aligned.m8n8.x2.shared.b16 {%0,%1}, [%2];"
                 : "=r"(r[0]), "=r"(r[1]) : "r"(a));
}
__device__ __forceinline__ void mma_bf16(float* c, const uint32_t* a,
                                         const uint32_t* b) {
    asm volatile(
        "mma.sync.aligned.m16n8k16.row.col.f32.bf16.bf16.f32 "
        "{%0,%1,%2,%3}, {%4,%5,%6,%7}, {%8,%9}, {%0,%1,%2,%3};"
        : "+f"(c[0]), "+f"(c[1]), "+f"(c[2]), "+f"(c[3])
        : "r"(a[0]), "r"(a[1]), "r"(a[2]), "r"(a[3]), "r"(b[0]), "r"(b[1]));
}

// swizzled byte offset of (row r, 16B-chunk kc) in a 128B-row tile
__device__ __forceinline__ uint32_t swz(int r, int kc) {
    return (uint32_t)r * 128u + (uint32_t)((kc ^ (r & 7)) << 4);
}

// folded K given fs and T: P = 60*fs; fold only if exact and well-aligned
__device__ __forceinline__ int fold_len(int fs, int T) {
    int P = 60 * fs;
    if (P > 0 && P < T && (T % P) == 0 && (P % 8) == 0) return P;
    return T;
}

// ---------------------------------------------------------------------------
// K1: fused prep. idx < n4: fold x across periods (fp32) -> bf16 hi/lo.
//     idx >= n4: basis element for t < Tf (JAX fp32 rounding, DP reduction).
// ---------------------------------------------------------------------------
__global__ void prep_kernel(const float* __restrict__ x,
                            const int* __restrict__ fs_p,
                            const int* __restrict__ samp_p,
                            const int* __restrict__ fmin_p,
                            const int* __restrict__ fmax_p,
                            int T, int n4, int nbasis) {
    int idx = blockIdx.x * blockDim.x + threadIdx.x;
    const int fs = *fs_p;
    const int Tf = fold_len(fs, T);
    if (idx == 0) g_Tf = Tf;

    if (idx < n4) {
        const int tq4 = T >> 2;                  // float4s per input row
        const int b   = idx / tq4;
        const int tq  = idx - b * tq4;
        if (tq * 4 >= Tf) return;                // only first period writes
        float4 v = ((const float4*)x)[idx];
        for (int j = Tf; j < T; j += Tf) {       // fold later periods in fp32
            float4 w = ((const float4*)x)[idx + (j >> 2)];
            v.x += w.x; v.y += w.y; v.z += w.z; v.w += w.w;
        }
        float vv[4] = {v.x, v.y, v.z, v.w};
        unsigned short hs[4], ls[4];
#pragma unroll
        for (int j = 0; j < 4; j++) {
            __nv_bfloat16 h = __float2bfloat16(vv[j]);
            float r = vv[j] - __bfloat162float(h);
            hs[j] = __bfloat16_as_ushort(h);
            ls[j] = __bfloat16_as_ushort(__float2bfloat16(r));
        }
        const int o = b * (Tf >> 2) + tq;        // output stride = Tf
        ((uint2*)g_xhi)[o] = make_uint2((uint32_t)hs[0] | ((uint32_t)hs[1] << 16),
                                        (uint32_t)hs[2] | ((uint32_t)hs[3] << 16));
        ((uint2*)g_xlo)[o] = make_uint2((uint32_t)ls[0] | ((uint32_t)ls[1] << 16),
                                        (uint32_t)ls[2] | ((uint32_t)ls[3] << 16));
        return;
    }
    int bi = idx - n4;
    if (bi >= nbasis) return;
    int c = bi / T;
    int t = bi - c * T;
    if (t >= Tf) return;

    int samp = *samp_p, fmin = *fmin_p, fmax = *fmax_p;
    int ngrid = (fmax - fmin) / samp + 1;

    float v = 0.0f;
    if (c < 2 * ngrid) {
        int g = c >> 1;
        float fHz = (float)(fmin + g * samp) / 60.0f;
        float s   = (float)(6.283185307179586 / (double)fs);
        float ph  = (s * fHz) * (float)t;            // JAX fp32 rounding order
        double dph = (double)ph;
        double r = dph - floor(dph * 0.15915494309189535) * 6.283185307179586;
        if (r > 3.141592653589793) r -= 6.283185307179586;
        float rf = (float)r;
        v = (c & 1) ? sinf(rf) : cosf(rf);
    }
    __nv_bfloat16 h = __float2bfloat16(v);
    float rlo = v - __bfloat162float(h);
    g_whi[(size_t)c * Tf + t] = h;                   // stride = Tf
    g_wlo[(size_t)c * Tf + t] = __float2bfloat16(rlo);
}

// ---------------------------------------------------------------------------
// K2: GEMM via mma.sync. grid (B/128, 448/112); 512 thr = 16 warps (8m x 2n).
// Warp tile 16m x 56n; fragments m16n8k16. K = g_Tf (device). psd direct.
// ---------------------------------------------------------------------------
extern __shared__ __align__(128) uint8_t dynsm[];

__global__ __launch_bounds__(512, 1) void gemm_mma(int Brows) {
    const int Tf = g_Tf;
    const int chunks = (Tf + KC - 1) / KC;

    const int tid  = threadIdx.x;
    const int lane = tid & 31;
    const int warp = tid >> 5;
    const int wm   = warp & 7;        // 0..7 -> 16-row slice
    const int wn   = warp >> 3;       // 0..1 -> 56-col slice
    const int rowBase = blockIdx.x * BM;
    const int colBase = blockIdx.y * BN;

    const uint32_t smb = smem_u32(dynsm);

    const __nv_bfloat16* Ah = g_xhi + (size_t)rowBase * Tf;
    const __nv_bfloat16* Al = g_xlo + (size_t)rowBase * Tf;
    const __nv_bfloat16* Bh = g_whi + (size_t)colBase * Tf;
    const __nv_bfloat16* Bl = g_wlo + (size_t)colBase * Tf;

    float acc[7][4];
#pragma unroll
    for (int j = 0; j < 7; j++)
#pragma unroll
        for (int q = 0; q < 4; q++) acc[j][q] = 0.f;

    // ---- fill one buffer with chunk (cp.async, zfill OOB-K) ----
    auto fill = [&](int buf, int chunk) {
        const int k0 = chunk * KC;
        const uint32_t bb = smb + (uint32_t)buf * BUF_BYTES;
        for (int idx = tid; idx < 3840; idx += 512) {
            const __nv_bfloat16* src;
            uint32_t sec;
            int s = idx, r;
            if (idx < 2048) {
                if (s < 1024) { sec = SM_AH; src = Ah; }
                else          { sec = SM_AL; src = Al; s -= 1024; }
            } else {
                s = idx - 2048;
                if (s < 896)  { sec = SM_BH; src = Bh; }
                else          { sec = SM_BL; src = Bl; s -= 896; }
            }
            r = s >> 3;
            const int c = s & 7;
            const int k = k0 + c * 8;
            cp_async16(bb + sec + swz(r, c), src + (size_t)r * Tf + k,
                       (k < Tf) ? 16 : 0);
        }
    };

    // ---- compute one buffered chunk: 4 k16-steps ----
    auto compute = [&](int buf) {
        const uint32_t bb = smb + (uint32_t)buf * BUF_BYTES;
#pragma unroll
        for (int ks = 0; ks < 4; ks++) {
            uint32_t ah[4], al[4], bh[7][2], bl[7][2];
            {
                const int rA  = wm * 16 + (lane & 15);
                const int kcA = ks * 2 + (lane >> 4);
                const uint32_t off = swz(rA, kcA);
                ldsm4(ah, bb + SM_AH + off);
                ldsm4(al, bb + SM_AL + off);
            }
            {
                const int rb  = ((lane >> 4) & 1) * 8 + (lane & 7);
                const int kcB = ks * 2 + ((lane >> 3) & 1);
#pragma unroll
                for (int jp = 0; jp < 3; jp++) {
                    const int r = wn * 56 + jp * 16 + rb;
                    const uint32_t off = swz(r, kcB);
                    uint32_t t4[4];
                    ldsm4(t4, bb + SM_BH + off);
                    bh[2 * jp][0] = t4[0]; bh[2 * jp][1] = t4[1];
                    bh[2 * jp + 1][0] = t4[2]; bh[2 * jp + 1][1] = t4[3];
                    ldsm4(t4, bb + SM_BL + off);
                    bl[2 * jp][0] = t4[0]; bl[2 * jp][1] = t4[1];
                    bl[2 * jp + 1][0] = t4[2]; bl[2 * jp + 1][1] = t4[3];
                }
                {   // j=6 via x2 (lanes 0-15 supply addresses)
                    const int r = wn * 56 + 48 + (lane & 7);
                    const int kc2 = ks * 2 + ((lane >> 3) & 1);
                    const uint32_t off = swz(r, kc2);
                    ldsm2(bh[6], bb + SM_BH + off);
                    ldsm2(bl[6], bb + SM_BL + off);
                }
            }
#pragma unroll
            for (int j = 0; j < 7; j++) {
                mma_bf16(acc[j], ah, bh[j]);
                mma_bf16(acc[j], ah, bl[j]);
                mma_bf16(acc[j], al, bh[j]);
            }
        }
    };

    // ---- double-buffered mainloop ----
    fill(0, 0);
    CP_COMMIT();
    int buf = 0;
    for (int c = 0; c < chunks; ++c) {
        if (c + 1 < chunks) { fill(buf ^ 1, c + 1); CP_COMMIT(); }
        if (c + 1 < chunks) CP_WAIT(1); else CP_WAIT(0);
        __syncthreads();
        compute(buf);
        __syncthreads();
        buf ^= 1;
    }

    // ---- epilogue: psd = c_even^2 + c_odd^2, write directly ----
#pragma unroll
    for (int j = 0; j < 7; j++) {
        const int row = rowBase + wm * 16 + (lane >> 2);
        const int g   = (colBase >> 1) + wn * 28 + j * 4 + (lane & 3);
        const float* cc = acc[j];
        g_psd[(size_t)row * GMAX + g]       = cc[0] * cc[0] + cc[1] * cc[1];
        g_psd[(size_t)(row + 8) * GMAX + g] = cc[2] * cc[2] + cc[3] * cc[3];
    }
}

// ---------------------------------------------------------------------------
// K3: per-row SNR. One warp per row.
// ---------------------------------------------------------------------------
__global__ void snr_kernel(const int* __restrict__ ftrue,
                           const int* __restrict__ samp_p,
                           const int* __restrict__ delta_p,
                           const int* __restrict__ fmin_p,
                           const int* __restrict__ fmax_p,
                           int B) {
    int row  = blockIdx.x * (blockDim.x >> 5) + (threadIdx.x >> 5);
    int lane = threadIdx.x & 31;
    if (row >= B) return;

    int samp = *samp_p, delta = *delta_p, fmin = *fmin_p, fmax = *fmax_p;
    int ngrid = (fmax - fmin) / samp + 1;
    int f = ftrue[row];

    float tot = 0.f, wan = 0.f;
    for (int g = lane; g < ngrid; g += 32) {
        float p = g_psd[(size_t)row * GMAX + g];
        tot += p;
        int d = fmin + g * samp - f;
        if (d < 0) d = -d;
        if (d <= delta) wan += p;
    }
#pragma unroll
    for (int o = 16; o > 0; o >>= 1) {
        tot += __shfl_xor_sync(0xFFFFFFFFu, tot, o);
        wan += __shfl_xor_sync(0xFFFFFFFFu, wan, o);
    }
    if (lane == 0) {
        int nw = 2 * delta / samp + 1;
        int nu = ngrid - nw;
        float t1 = wan / (float)nw;
        float t2 = (tot - wan) / (float)nu;
        g_snr[row] = 10.0f * log10f(t1 / t2);
    }
}

// ---------------------------------------------------------------------------
// K4: -mean(snr), 1024 threads + shuffle reduction
// ---------------------------------------------------------------------------
__global__ void mean_kernel(float* __restrict__ out, int B) {
    __shared__ float red[32];
    const int tid = threadIdx.x, lane = tid & 31, wid = tid >> 5;
    float s = 0.f;
    for (int i = tid; i < B; i += 1024) s += g_snr[i];
#pragma unroll
    for (int o = 16; o > 0; o >>= 1) s += __shfl_xor_sync(0xFFFFFFFFu, s, o);
    if (lane == 0) red[wid] = s;
    __syncthreads();
    if (wid == 0) {
        s = red[lane];
#pragma unroll
        for (int o = 16; o > 0; o >>= 1) s += __shfl_xor_sync(0xFFFFFFFFu, s, o);
        if (lane == 0) out[0] = -(s / (float)B);
    }
}

// ---------------------------------------------------------------------------
extern "C" void kernel_launch(void* const* d_in, const int* in_sizes, int n_in,
                              void* d_out, int out_size) {
    const float* x     = (const float*)d_in[0];
    const int*   ftrue = (const int*)  d_in[1];
    const int*   fs    = (const int*)  d_in[2];
    const int*   delta = (const int*)  d_in[3];
    const int*   samp  = (const int*)  d_in[4];
    const int*   fmin  = (const int*)  d_in[5];
    const int*   fmax  = (const int*)  d_in[6];

    const int B = in_sizes[1];
    const int T = in_sizes[0] / B;

    const int n4 = (B * T) / 4;
    const int nbasis = NCOLS * T;
    prep_kernel<<<(n4 + nbasis + 255) / 256, 256>>>(x, fs, samp, fmin, fmax,
                                                    T, n4, nbasis);

    cudaFuncSetAttribute(gemm_mma, cudaFuncAttributeMaxDynamicSharedMemorySize,
                         SMEM_TOTAL);
    gemm_mma<<<dim3(B / BM, NCOLS / BN), 512, SMEM_TOTAL>>>(B);

    snr_kernel<<<(B + 7) / 8, 256>>>(ftrue, samp, delta, fmin, fmax, B);
    mean_kernel<<<1, 1024>>>((float*)d_out, B);
}

// round 10
// speedup vs baseline: 7.3753x; 1.8971x over previous
#include <cuda_runtime.h>
#include <cuda_fp16.h>
#include <math.h>
#include <stdint.h>

// ===========================================================================
// ExtractorLoss via fp16 tensor-core GEMM (mma.sync) with half-period DFT
// folding:
//   W[g, t + 30*fs] = (-1)^f_bpm * W[g, t]  exactly (phase step = pi*f).
//   Fold x into x_e (even-bpm bins) and x_o = alternating-sign fold (odd bins)
//   => K: T -> 30*fs (=900), N per class ~202. Single fp16 MMA term suffices
//   (error budget ~1e-4 vs 1e-3 gate; calibrated against R8 measurements).
//   K1 prep  : fold x -> fp16 x_e/x_o ; basis (JAX fp32 phase) -> fp16 by class
//   K2 gemm  : acc = A16 * W16 (fp32 accum), psd = a^2+b^2 in-register
//   K3 snr   : masked means per row, 10*log10
//   K4 mean  : -mean(snr)
// ===========================================================================

#define BMAX   4096
#define TMAXE  3648
#define NCOLS  448          // 2 classes x 224 padded cols
#define GMAX   224
#define BM     128
#define BN     112
#define KC     64           // K elems per chunk: 128B rows in smem

__device__ __align__(16) __half g_xe[BMAX * TMAXE];       // even-class fold
__device__ __align__(16) __half g_xo[BMAX * TMAXE];       // odd-class fold
__device__ __align__(16) __half g_w16[2 * 224 * TMAXE];   // [class][col][t]
__device__ __align__(16) float g_psd[BMAX * GMAX];
__device__ float g_snr[BMAX];

// smem per buffer: A(128 rows x 128B = 16K) + B(112 rows = 14K) = 30K; x2
#define SM_A 0u
#define SM_B 16384u
#define BUF_BYTES 30720u
#define SMEM_TOTAL (2u * BUF_BYTES)

// ---------------- PTX helpers ----------------------------------------------
__device__ __forceinline__ uint32_t smem_u32(const void* p) {
    uint32_t a;
    asm("{ .reg .u64 t; cvta.to.shared.u64 t, %1; cvt.u32.u64 %0, t; }"
        : "=r"(a) : "l"(p));
    return a;
}
__device__ __forceinline__ void cp_async16(uint32_t dst, const void* src, int sz) {
    asm volatile("cp.async.cg.shared.global [%0], [%1], 16, %2;"
                 :: "r"(dst), "l"(src), "r"(sz) : "memory");
}
#define CP_COMMIT() asm volatile("cp.async.commit_group;" ::: "memory")
#define CP_WAIT(n)  asm volatile("cp.async.wait_group %0;" :: "n"(n) : "memory")

__device__ __forceinline__ void ldsm4(uint32_t* r, uint32_t a) {
    asm volatile("ldmatrix.sync.aligned.m8n8.x4.shared.b16 {%0,%1,%2,%3}, [%4];"
                 : "=r"(r[0]), "=r"(r[1]), "=r"(r[2]), "=r"(r[3]) : "r"(a));
}
__device__ __forceinline__ void ldsm2(uint32_t* r, uint32_t a) {
    asm volatile("ldmatrix.sync.aligned.m8n8.x2.shared.b16 {%0,%1}, [%2];"
                 : "=r"(r[0]), "=r"(r[1]) : "r"(a));
}
__device__ __forceinline__ void mma_f16(float* c, const uint32_t* a,
                                        const uint32_t* b) {
    asm volatile(
        "mma.sync.aligned.m16n8k16.row.col.f32.f16.f16.f32 "
        "{%0,%1,%2,%3}, {%4,%5,%6,%7}, {%8,%9}, {%0,%1,%2,%3};"
        : "+f"(c[0]), "+f"(c[1]), "+f"(c[2]), "+f"(c[3])
        : "r"(a[0]), "r"(a[1]), "r"(a[2]), "r"(a[3]), "r"(b[0]), "r"(b[1]));
}

// swizzled byte offset of (row r, 16B-chunk kc) in a 128B-row tile
__device__ __forceinline__ uint32_t swz(int r, int kc) {
    return (uint32_t)r * 128u + (uint32_t)((kc ^ (r & 7)) << 4);
}

// fold length + mode. half=1: parity classes over 30*fs. half=0: single class.
__device__ __forceinline__ int fold_info(int fs, int T, int* half) {
    int P2 = 30 * fs;
    if (P2 > 0 && P2 <= T && (T % P2) == 0) { *half = 1; return P2; }
    int P = 60 * fs;
    if (P > 0 && P <= T && (T % P) == 0) { *half = 0; return P; }
    *half = 0;
    return T;
}

// class/local-bin mapping helpers (must agree between prep and gemm epilogue)
__device__ __forceinline__ int bin_class(int g, int fmin, int samp, int half) {
    return half ? ((fmin + g * samp) & 1) : 0;
}
__device__ __forceinline__ int bin_local(int g, int samp, int half) {
    return (half && (samp & 1)) ? (g >> 1) : g;
}
// inverse: local j of class P -> global g; returns count nP via *np
__device__ __forceinline__ void class_geom(int P, int fmin, int samp, int ngrid,
                                           int half, int* gstart, int* gstep,
                                           int* np) {
    if (half) {
        if (samp & 1) {
            int gs = (P == (fmin & 1)) ? 0 : 1;
            *gstart = gs; *gstep = 2;
            *np = (gs < ngrid) ? ((ngrid - gs + 1) >> 1) : 0;
        } else {
            if (P == (fmin & 1)) { *gstart = 0; *gstep = 1; *np = ngrid; }
            else                 { *gstart = 0; *gstep = 1; *np = 0; }
        }
    } else {
        if (P == 0) { *gstart = 0; *gstep = 1; *np = ngrid; }
        else        { *gstart = 0; *gstep = 1; *np = 0; }
    }
}

// ---------------------------------------------------------------------------
// K1: prep. idx < B*T/4: fold x (float4 path; falls back to skip if t>=Tfold).
//     idx >= B*T/4: basis element (JAX fp32 rounding, DP range reduction).
// Pad regions [Tfold, Kp) are never written; __device__ globals are
// zero-initialized, so they read as exact zeros in the GEMM.
// ---------------------------------------------------------------------------
__global__ void prep_kernel(const float* __restrict__ x,
                            const int* __restrict__ fs_p,
                            const int* __restrict__ samp_p,
                            const int* __restrict__ fmin_p,
                            const int* __restrict__ fmax_p,
                            int T, int nx4, int nbasis) {
    int idx = blockIdx.x * blockDim.x + threadIdx.x;
    const int fs = *fs_p;
    int half;
    const int Tfold = fold_info(fs, T, &half);
    const int Kp = (Tfold + 7) & ~7;           // storage row stride (halfs)
    const int nper = T / Tfold;

    if (idx < nx4) {
        // x fold: float4 over first period (requires Tfold%4==0 && T%4==0,
        // true for all practical fs; guarded below)
        if ((Tfold & 3) == 0 && (T & 3) == 0) {
            const int tq4 = T >> 2;
            const int b   = idx / tq4;
            const int t   = (idx - b * tq4) << 2;
            if (t >= Tfold) return;
            float4 se = make_float4(0.f, 0.f, 0.f, 0.f);
            float4 so = se;
            const float* base = x + (size_t)b * T + t;
#pragma unroll 4
            for (int j = 0; j < nper; j++) {
                float4 v = *(const float4*)(base + j * Tfold);
                se.x += v.x; se.y += v.y; se.z += v.z; se.w += v.w;
                float sg = (j & 1) ? -1.f : 1.f;
                so.x += sg * v.x; so.y += sg * v.y;
                so.z += sg * v.z; so.w += sg * v.w;
            }
            __half* pe = g_xe + (size_t)b * Kp + t;
            pe[0] = __float2half_rn(se.x); pe[1] = __float2half_rn(se.y);
            pe[2] = __float2half_rn(se.z); pe[3] = __float2half_rn(se.w);
            if (half) {
                __half* po = g_xo + (size_t)b * Kp + t;
                po[0] = __float2half_rn(so.x); po[1] = __float2half_rn(so.y);
                po[2] = __float2half_rn(so.z); po[3] = __float2half_rn(so.w);
            }
        } else {
            // scalar fallback: each of the 4 elements this thread owns
            const int tq4 = T >> 2;
            const int b   = idx / tq4;
            const int t0  = (idx - b * tq4) << 2;
            for (int u = 0; u < 4; u++) {
                int t = t0 + u;
                if (t >= Tfold) break;
                float se = 0.f, so = 0.f;
                for (int j = 0; j < nper; j++) {
                    float v = x[(size_t)b * T + t + j * Tfold];
                    se += v;
                    so += (j & 1) ? -v : v;
                }
                g_xe[(size_t)b * Kp + t] = __float2half_rn(se);
                if (half) g_xo[(size_t)b * Kp + t] = __float2half_rn(so);
            }
        }
        return;
    }
    int bi = idx - nx4;
    if (bi >= nbasis) return;
    int c = bi / T;
    int t = bi - c * T;
    if (t >= Tfold) return;

    int samp = *samp_p, fmin = *fmin_p, fmax = *fmax_p;
    int ngrid = (fmax - fmin) / samp + 1;
    if (c >= 2 * ngrid) return;

    int g = c >> 1;
    float fHz = (float)(fmin + g * samp) / 60.0f;
    float s   = (float)(6.283185307179586 / (double)fs);
    float ph  = (s * fHz) * (float)t;            // JAX fp32 rounding order
    double dph = (double)ph;
    double r = dph - floor(dph * 0.15915494309189535) * 6.283185307179586;
    if (r > 3.141592653589793) r -= 6.283185307179586;
    float rf = (float)r;
    float v = (c & 1) ? sinf(rf) : cosf(rf);

    const int P = bin_class(g, fmin, samp, half);
    const int j = bin_local(g, samp, half);
    const int col = 2 * j + (c & 1);
    g_w16[((size_t)P * 224 + col) * Kp + t] = __float2half_rn(v);
}

// ---------------------------------------------------------------------------
// K2: GEMM via mma.sync. grid (B/128, 2 Ntiles, 2 classes); 512 thr =
// 16 warps (8m x 2n). Warp tile 16m x 56n; fragments m16n8k16. psd direct.
// ---------------------------------------------------------------------------
extern __shared__ __align__(128) uint8_t dynsm[];

__global__ __launch_bounds__(512, 1) void gemm_mma(const int* __restrict__ fs_p,
                                                   const int* __restrict__ samp_p,
                                                   const int* __restrict__ fmin_p,
                                                   const int* __restrict__ fmax_p,
                                                   int Brows, int T) {
    const int fs = *fs_p, samp = *samp_p, fmin = *fmin_p, fmax = *fmax_p;
    int half;
    const int Tfold = fold_info(fs, T, &half);
    const int Kp = (Tfold + 7) & ~7;
    const int chunks = (Kp + KC - 1) / KC;
    const int ngrid = (fmax - fmin) / samp + 1;

    const int P = blockIdx.z;
    int gstart, gstep, nP;
    class_geom(P, fmin, samp, ngrid, half, &gstart, &gstep, &nP);
    if (nP == 0) return;                       // empty class (uniform exit)

    const int tid  = threadIdx.x;
    const int lane = tid & 31;
    const int warp = tid >> 5;
    const int wm   = warp & 7;        // 0..7 -> 16-row slice
    const int wn   = warp >> 3;       // 0..1 -> 56-col slice
    const int rowBase = blockIdx.x * BM;
    const int colBase = blockIdx.y * BN;

    const uint32_t smb = smem_u32(dynsm);

    const __half* A = (P == 0 ? g_xe : g_xo) + (size_t)rowBase * Kp;
    const __half* Bw = g_w16 + ((size_t)P * 224 + colBase) * Kp;

    float acc[7][4];
#pragma unroll
    for (int j = 0; j < 7; j++)
#pragma unroll
        for (int q = 0; q < 4; q++) acc[j][q] = 0.f;

    // ---- fill one buffer with chunk (cp.async, zfill OOB-K) ----
    auto fill = [&](int buf, int chunk) {
        const int k0 = chunk * KC;
        const uint32_t bb = smb + (uint32_t)buf * BUF_BYTES;
        for (int idx = tid; idx < 1920; idx += 512) {
            const __half* src;
            uint32_t sec;
            int r;
            if (idx < 1024) { sec = SM_A; src = A;  r = idx >> 3; }
            else            { sec = SM_B; src = Bw; r = (idx - 1024) >> 3; }
            const int c = idx & 7;
            const int k = k0 + c * 8;
            cp_async16(bb + sec + swz(r, c), src + (size_t)r * Kp + k,
                       (k < Kp) ? 16 : 0);
        }
    };

    // ---- compute one buffered chunk: 4 k16-steps ----
    auto compute = [&](int buf) {
        const uint32_t bb = smb + (uint32_t)buf * BUF_BYTES;
#pragma unroll
        for (int ks = 0; ks < 4; ks++) {
            uint32_t a4[4], bfr[7][2];
            {
                const int rA  = wm * 16 + (lane & 15);
                const int kcA = ks * 2 + (lane >> 4);
                ldsm4(a4, bb + SM_A + swz(rA, kcA));
            }
            {
                const int rb  = ((lane >> 4) & 1) * 8 + (lane & 7);
                const int kcB = ks * 2 + ((lane >> 3) & 1);
#pragma unroll
                for (int jp = 0; jp < 3; jp++) {
                    const int r = wn * 56 + jp * 16 + rb;
                    uint32_t t4[4];
                    ldsm4(t4, bb + SM_B + swz(r, kcB));
                    bfr[2 * jp][0] = t4[0]; bfr[2 * jp][1] = t4[1];
                    bfr[2 * jp + 1][0] = t4[2]; bfr[2 * jp + 1][1] = t4[3];
                }
                {   // j=6 via x2 (lanes 0-15 supply addresses)
                    const int r = wn * 56 + 48 + (lane & 7);
                    const int kc2 = ks * 2 + ((lane >> 3) & 1);
                    ldsm2(bfr[6], bb + SM_B + swz(r, kc2));
                }
            }
#pragma unroll
            for (int j = 0; j < 7; j++) mma_f16(acc[j], a4, bfr[j]);
        }
    };

    // ---- double-buffered mainloop ----
    fill(0, 0);
    CP_COMMIT();
    int buf = 0;
    for (int c = 0; c < chunks; ++c) {
        if (c + 1 < chunks) { fill(buf ^ 1, c + 1); CP_COMMIT(); }
        if (c + 1 < chunks) CP_WAIT(1); else CP_WAIT(0);
        __syncthreads();
        compute(buf);
        __syncthreads();
        buf ^= 1;
    }

    // ---- epilogue: psd = c_even^2 + c_odd^2 -> global bin via class map ----
#pragma unroll
    for (int j = 0; j < 7; j++) {
        const int row = rowBase + wm * 16 + (lane >> 2);
        const int jl  = (colBase >> 1) + wn * 28 + j * 4 + (lane & 3);
        if (jl < nP) {
            const int g = gstart + jl * gstep;
            const float* cc = acc[j];
            g_psd[(size_t)row * GMAX + g]       = cc[0] * cc[0] + cc[1] * cc[1];
            g_psd[(size_t)(row + 8) * GMAX + g] = cc[2] * cc[2] + cc[3] * cc[3];
        }
    }
}

// ---------------------------------------------------------------------------
// K3: per-row SNR. One warp per row.
// ---------------------------------------------------------------------------
__global__ void snr_kernel(const int* __restrict__ ftrue,
                           const int* __restrict__ samp_p,
                           const int* __restrict__ delta_p,
                           const int* __restrict__ fmin_p,
                           const int* __restrict__ fmax_p,
                           int B) {
    int row  = blockIdx.x * (blockDim.x >> 5) + (threadIdx.x >> 5);
    int lane = threadIdx.x & 31;
    if (row >= B) return;

    int samp = *samp_p, delta = *delta_p, fmin = *fmin_p, fmax = *fmax_p;
    int ngrid = (fmax - fmin) / samp + 1;
    int f = ftrue[row];

    float tot = 0.f, wan = 0.f;
    for (int g = lane; g < ngrid; g += 32) {
        float p = g_psd[(size_t)row * GMAX + g];
        tot += p;
        int d = fmin + g * samp - f;
        if (d < 0) d = -d;
        if (d <= delta) wan += p;
    }
#pragma unroll
    for (int o = 16; o > 0; o >>= 1) {
        tot += __shfl_xor_sync(0xFFFFFFFFu, tot, o);
        wan += __shfl_xor_sync(0xFFFFFFFFu, wan, o);
    }
    if (lane == 0) {
        int nw = 2 * delta / samp + 1;
        int nu = ngrid - nw;
        float t1 = wan / (float)nw;
        float t2 = (tot - wan) / (float)nu;
        g_snr[row] = 10.0f * log10f(t1 / t2);
    }
}

// ---------------------------------------------------------------------------
// K4: -mean(snr), 1024 threads + shuffle reduction
// ---------------------------------------------------------------------------
__global__ void mean_kernel(float* __restrict__ out, int B) {
    __shared__ float red[32];
    const int tid = threadIdx.x, lane = tid & 31, wid = tid >> 5;
    float s = 0.f;
    for (int i = tid; i < B; i += 1024) s += g_snr[i];
#pragma unroll
    for (int o = 16; o > 0; o >>= 1) s += __shfl_xor_sync(0xFFFFFFFFu, s, o);
    if (lane == 0) red[wid] = s;
    __syncthreads();
    if (wid == 0) {
        s = red[lane];
#pragma unroll
        for (int o = 16; o > 0; o >>= 1) s += __shfl_xor_sync(0xFFFFFFFFu, s, o);
        if (lane == 0) out[0] = -(s / (float)B);
    }
}

// ---------------------------------------------------------------------------
extern "C" void kernel_launch(void* const* d_in, const int* in_sizes, int n_in,
                              void* d_out, int out_size) {
    const float* x     = (const float*)d_in[0];
    const int*   ftrue = (const int*)  d_in[1];
    const int*   fs    = (const int*)  d_in[2];
    const int*   delta = (const int*)  d_in[3];
    const int*   samp  = (const int*)  d_in[4];
    const int*   fmin  = (const int*)  d_in[5];
    const int*   fmax  = (const int*)  d_in[6];

    const int B = in_sizes[1];
    const int T = in_sizes[0] / B;

    const int nx4 = (B * T) / 4;
    const int nbasis = NCOLS * T;
    prep_kernel<<<(nx4 + nbasis + 255) / 256, 256>>>(x, fs, samp, fmin, fmax,
                                                     T, nx4, nbasis);

    cudaFuncSetAttribute(gemm_mma, cudaFuncAttributeMaxDynamicSharedMemorySize,
                         SMEM_TOTAL);
    gemm_mma<<<dim3(B / BM, 2, 2), 512, SMEM_TOTAL>>>(fs, samp, fmin, fmax,
                                                      B, T);

    snr_kernel<<<(B + 7) / 8, 256>>>(ftrue, samp, delta, fmin, fmax, B);
    mean_kernel<<<1, 1024>>>((float*)d_out, B);
}

// round 11
// speedup vs baseline: 11.0899x; 1.5036x over previous
#include <cuda_runtime.h>
#include <cuda_fp16.h>
#include <math.h>
#include <stdint.h>

// ===========================================================================
// ExtractorLoss, fp16 mma.sync GEMM + half-period DFT fold + fused reduction:
//   K1 prep     : zero accumulators; fold x -> fp16 x_e/x_o; basis -> fp16
//                 (grid-stride over device-computed work counts)
//   K2 gemm     : acc = A16*W16 (fp32), psd=a^2+b^2 in-register, then
//                 per-row (tot, wanted) partial sums -> fixed-point u64 atomics
//   K3 finalize : snr per row + deterministic mean -> out[0]
// ===========================================================================

#define BMAX   4096
#define TMAXE  3648
#define GMAX   224
#define BM     128
#define BN     112
#define KC     64           // K elems per chunk: 128B rows in smem
#define FIXS   1048576.0f   // 2^20 fixed-point scale (associative -> deterministic)

__device__ __align__(16) __half g_xe[BMAX * TMAXE];       // even-class fold
__device__ __align__(16) __half g_xo[BMAX * TMAXE];       // odd-class fold
__device__ __align__(16) __half g_w16[2 * 224 * TMAXE];   // [class][col][t]
__device__ unsigned long long g_acc[BMAX * 2];            // [row]{tot,wan} fixed-pt

// smem per buffer: A(128 rows x 128B = 16K) + B(112 rows = 14K) = 30K; x2
#define SM_A 0u
#define SM_B 16384u
#define BUF_BYTES 30720u
#define SMEM_TOTAL (2u * BUF_BYTES)

// ---------------- PTX helpers ----------------------------------------------
__device__ __forceinline__ uint32_t smem_u32(const void* p) {
    uint32_t a;
    asm("{ .reg .u64 t; cvta.to.shared.u64 t, %1; cvt.u32.u64 %0, t; }"
        : "=r"(a) : "l"(p));
    return a;
}
__device__ __forceinline__ void cp_async16(uint32_t dst, const void* src, int sz) {
    asm volatile("cp.async.cg.shared.global [%0], [%1], 16, %2;"
                 :: "r"(dst), "l"(src), "r"(sz) : "memory");
}
#define CP_COMMIT() asm volatile("cp.async.commit_group;" ::: "memory")
#define CP_WAIT(n)  asm volatile("cp.async.wait_group %0;" :: "n"(n) : "memory")

__device__ __forceinline__ void ldsm4(uint32_t* r, uint32_t a) {
    asm volatile("ldmatrix.sync.aligned.m8n8.x4.shared.b16 {%0,%1,%2,%3}, [%4];"
                 : "=r"(r[0]), "=r"(r[1]), "=r"(r[2]), "=r"(r[3]) : "r"(a));
}
__device__ __forceinline__ void ldsm2(uint32_t* r, uint32_t a) {
    asm volatile("ldmatrix.sync.aligned.m8n8.x2.shared.b16 {%0,%1}, [%2];"
                 : "=r"(r[0]), "=r"(r[1]) : "r"(a));
}
__device__ __forceinline__ void mma_f16(float* c, const uint32_t* a,
                                        const uint32_t* b) {
    asm volatile(
        "mma.sync.aligned.m16n8k16.row.col.f32.f16.f16.f32 "
        "{%0,%1,%2,%3}, {%4,%5,%6,%7}, {%8,%9}, {%0,%1,%2,%3};"
        : "+f"(c[0]), "+f"(c[1]), "+f"(c[2]), "+f"(c[3])
        : "r"(a[0]), "r"(a[1]), "r"(a[2]), "r"(a[3]), "r"(b[0]), "r"(b[1]));
}

// swizzled byte offset of (row r, 16B-chunk kc) in a 128B-row tile
__device__ __forceinline__ uint32_t swz(int r, int kc) {
    return (uint32_t)r * 128u + (uint32_t)((kc ^ (r & 7)) << 4);
}

// fold length + mode. half=1: parity classes over 30*fs. half=0: single class.
__device__ __forceinline__ int fold_info(int fs, int T, int* half) {
    int P2 = 30 * fs;
    if (P2 > 0 && P2 <= T && (T % P2) == 0) { *half = 1; return P2; }
    int P = 60 * fs;
    if (P > 0 && P <= T && (T % P) == 0) { *half = 0; return P; }
    *half = 0;
    return T;
}

// class/local-bin mapping helpers (must agree between prep and gemm epilogue)
__device__ __forceinline__ int bin_class(int g, int fmin, int samp, int half) {
    return half ? ((fmin + g * samp) & 1) : 0;
}
__device__ __forceinline__ int bin_local(int g, int samp, int half) {
    return (half && (samp & 1)) ? (g >> 1) : g;
}
// inverse: local j of class P -> global g; returns count nP via *np
__device__ __forceinline__ void class_geom(int P, int fmin, int samp, int ngrid,
                                           int half, int* gstart, int* gstep,
                                           int* np) {
    if (half) {
        if (samp & 1) {
            int gs = (P == (fmin & 1)) ? 0 : 1;
            *gstart = gs; *gstep = 2;
            *np = (gs < ngrid) ? ((ngrid - gs + 1) >> 1) : 0;
        } else {
            if (P == (fmin & 1)) { *gstart = 0; *gstep = 1; *np = ngrid; }
            else                 { *gstart = 0; *gstep = 1; *np = 0; }
        }
    } else {
        if (P == 0) { *gstart = 0; *gstep = 1; *np = ngrid; }
        else        { *gstart = 0; *gstep = 1; *np = 0; }
    }
}

// ---------------------------------------------------------------------------
// K1: prep, grid-stride over [zero g_acc | fold items | basis items].
// Pad regions [Tfold, Kp) are never written; zero-init globals read as 0.
// ---------------------------------------------------------------------------
__global__ void prep_kernel(const float* __restrict__ x,
                            const int* __restrict__ fs_p,
                            const int* __restrict__ samp_p,
                            const int* __restrict__ fmin_p,
                            const int* __restrict__ fmax_p,
                            int T, int B) {
    const int fs = *fs_p, samp = *samp_p, fmin = *fmin_p, fmax = *fmax_p;
    int half;
    const int Tfold = fold_info(fs, T, &half);
    const int Kp = (Tfold + 7) & ~7;           // storage row stride (halfs)
    const int nper = T / Tfold;
    const int ngrid = (fmax - fmin) / samp + 1;
    const bool vec4 = ((Tfold & 3) == 0) && ((T & 3) == 0);

    const int tq = (Tfold + 3) >> 2;                   // 4-elem items per row
    const long long nzero  = 2ll * BMAX;
    const long long nfold  = (long long)B * tq;
    const long long nbasis = 2ll * ngrid * (long long)Tfold;
    const long long total  = nzero + nfold + nbasis;
    const long long stride = (long long)gridDim.x * blockDim.x;

    for (long long w = (long long)blockIdx.x * blockDim.x + threadIdx.x;
         w < total; w += stride) {
        if (w < nzero) { g_acc[w] = 0ull; continue; }
        long long w1 = w - nzero;
        if (w1 < nfold) {
            const int b = (int)(w1 / tq);
            const int t = ((int)(w1 - (long long)b * tq)) << 2;
            if (vec4) {
                float4 se = make_float4(0.f, 0.f, 0.f, 0.f);
                float4 so = se;
                const float* base = x + (size_t)b * T + t;
                for (int j = 0; j < nper; j++) {
                    float4 v = *(const float4*)(base + (size_t)j * Tfold);
                    se.x += v.x; se.y += v.y; se.z += v.z; se.w += v.w;
                    float sg = (j & 1) ? -1.f : 1.f;
                    so.x += sg * v.x; so.y += sg * v.y;
                    so.z += sg * v.z; so.w += sg * v.w;
                }
                __half* pe = g_xe + (size_t)b * Kp + t;
                pe[0] = __float2half_rn(se.x); pe[1] = __float2half_rn(se.y);
                pe[2] = __float2half_rn(se.z); pe[3] = __float2half_rn(se.w);
                if (half) {
                    __half* po = g_xo + (size_t)b * Kp + t;
                    po[0] = __float2half_rn(so.x); po[1] = __float2half_rn(so.y);
                    po[2] = __float2half_rn(so.z); po[3] = __float2half_rn(so.w);
                }
            } else {
                for (int u = 0; u < 4; u++) {
                    int t2 = t + u;
                    if (t2 >= Tfold) break;
                    float se = 0.f, so = 0.f;
                    for (int j = 0; j < nper; j++) {
                        float v = x[(size_t)b * T + t2 + (size_t)j * Tfold];
                        se += v;
                        so += (j & 1) ? -v : v;
                    }
                    g_xe[(size_t)b * Kp + t2] = __float2half_rn(se);
                    if (half) g_xo[(size_t)b * Kp + t2] = __float2half_rn(so);
                }
            }
            continue;
        }
        long long w2 = w1 - nfold;
        const int c = (int)(w2 / Tfold);
        const int t = (int)(w2 - (long long)c * Tfold);

        const int g = c >> 1;
        float fHz = (float)(fmin + g * samp) / 60.0f;
        float s   = (float)(6.283185307179586 / (double)fs);
        float ph  = (s * fHz) * (float)t;            // JAX fp32 rounding order
        double dph = (double)ph;
        double r = dph - floor(dph * 0.15915494309189535) * 6.283185307179586;
        if (r > 3.141592653589793) r -= 6.283185307179586;
        float rf = (float)r;
        float v = (c & 1) ? sinf(rf) : cosf(rf);

        const int P = bin_class(g, fmin, samp, half);
        const int j = bin_local(g, samp, half);
        const int col = 2 * j + (c & 1);
        g_w16[((size_t)P * 224 + col) * Kp + t] = __float2half_rn(v);
    }
}

// ---------------------------------------------------------------------------
// K2: GEMM via mma.sync. grid (B/128, 2 Ntiles, 2 classes); 512 thr =
// 16 warps (8m x 2n). Warp tile 16m x 56n. Epilogue: psd in-register ->
// per-row (tot, wanted) partials -> quad shuffle -> fixed-point u64 atomics.
// ---------------------------------------------------------------------------
extern __shared__ __align__(128) uint8_t dynsm[];

__global__ __launch_bounds__(512, 1) void gemm_mma(const int* __restrict__ ftrue,
                                                   const int* __restrict__ fs_p,
                                                   const int* __restrict__ samp_p,
                                                   const int* __restrict__ delta_p,
                                                   const int* __restrict__ fmin_p,
                                                   const int* __restrict__ fmax_p,
                                                   int Brows, int T) {
    const int fs = *fs_p, samp = *samp_p, fmin = *fmin_p, fmax = *fmax_p;
    const int delta = *delta_p;
    int half;
    const int Tfold = fold_info(fs, T, &half);
    const int Kp = (Tfold + 7) & ~7;
    const int chunks = (Kp + KC - 1) / KC;
    const int ngrid = (fmax - fmin) / samp + 1;

    const int P = blockIdx.z;
    int gstart, gstep, nP;
    class_geom(P, fmin, samp, ngrid, half, &gstart, &gstep, &nP);
    if (nP == 0) return;                       // empty class (uniform exit)

    const int tid  = threadIdx.x;
    const int lane = tid & 31;
    const int warp = tid >> 5;
    const int wm   = warp & 7;        // 0..7 -> 16-row slice
    const int wn   = warp >> 3;       // 0..1 -> 56-col slice
    const int rowBase = blockIdx.x * BM;
    const int colBase = blockIdx.y * BN;

    const uint32_t smb = smem_u32(dynsm);

    const __half* A = (P == 0 ? g_xe : g_xo) + (size_t)rowBase * Kp;
    const __half* Bw = g_w16 + ((size_t)P * 224 + colBase) * Kp;

    float acc[7][4];
#pragma unroll
    for (int j = 0; j < 7; j++)
#pragma unroll
        for (int q = 0; q < 4; q++) acc[j][q] = 0.f;

    // ---- fill one buffer with chunk (cp.async, zfill OOB-K) ----
    auto fill = [&](int buf, int chunk) {
        const int k0 = chunk * KC;
        const uint32_t bb = smb + (uint32_t)buf * BUF_BYTES;
        for (int idx = tid; idx < 1920; idx += 512) {
            const __half* src;
            uint32_t sec;
            int r;
            if (idx < 1024) { sec = SM_A; src = A;  r = idx >> 3; }
            else            { sec = SM_B; src = Bw; r = (idx - 1024) >> 3; }
            const int c = idx & 7;
            const int k = k0 + c * 8;
            cp_async16(bb + sec + swz(r, c), src + (size_t)r * Kp + k,
                       (k < Kp) ? 16 : 0);
        }
    };

    // ---- compute one buffered chunk: 4 k16-steps ----
    auto compute = [&](int buf) {
        const uint32_t bb = smb + (uint32_t)buf * BUF_BYTES;
#pragma unroll
        for (int ks = 0; ks < 4; ks++) {
            uint32_t a4[4], bfr[7][2];
            {
                const int rA  = wm * 16 + (lane & 15);
                const int kcA = ks * 2 + (lane >> 4);
                ldsm4(a4, bb + SM_A + swz(rA, kcA));
            }
            {
                const int rb  = ((lane >> 4) & 1) * 8 + (lane & 7);
                const int kcB = ks * 2 + ((lane >> 3) & 1);
#pragma unroll
                for (int jp = 0; jp < 3; jp++) {
                    const int r = wn * 56 + jp * 16 + rb;
                    uint32_t t4[4];
                    ldsm4(t4, bb + SM_B + swz(r, kcB));
                    bfr[2 * jp][0] = t4[0]; bfr[2 * jp][1] = t4[1];
                    bfr[2 * jp + 1][0] = t4[2]; bfr[2 * jp + 1][1] = t4[3];
                }
                {   // j=6 via x2 (lanes 0-15 supply addresses)
                    const int r = wn * 56 + 48 + (lane & 7);
                    const int kc2 = ks * 2 + ((lane >> 3) & 1);
                    ldsm2(bfr[6], bb + SM_B + swz(r, kc2));
                }
            }
#pragma unroll
            for (int j = 0; j < 7; j++) mma_f16(acc[j], a4, bfr[j]);
        }
    };

    // ---- double-buffered mainloop ----
    fill(0, 0);
    CP_COMMIT();
    int buf = 0;
    for (int c = 0; c < chunks; ++c) {
        if (c + 1 < chunks) { fill(buf ^ 1, c + 1); CP_COMMIT(); }
        if (c + 1 < chunks) CP_WAIT(1); else CP_WAIT(0);
        __syncthreads();
        compute(buf);
        __syncthreads();
        buf ^= 1;
    }

    // ---- fused epilogue: psd -> per-row masked partial sums -> atomics ----
    {
        const int row0 = rowBase + wm * 16 + (lane >> 2);   // and row0+8
        const int f0 = ftrue[row0];
        const int f1 = ftrue[row0 + 8];
        float t0 = 0.f, w0 = 0.f, t1 = 0.f, w1 = 0.f;
#pragma unroll
        for (int j = 0; j < 7; j++) {
            const int jl = (colBase >> 1) + wn * 28 + j * 4 + (lane & 3);
            if (jl < nP) {
                const int g  = gstart + jl * gstep;
                const int fb = fmin + g * samp;
                const float* cc = acc[j];
                const float p0 = cc[0] * cc[0] + cc[1] * cc[1];
                const float p1 = cc[2] * cc[2] + cc[3] * cc[3];
                t0 += p0; t1 += p1;
                int d0 = fb - f0; if (d0 < 0) d0 = -d0;
                int d1 = fb - f1; if (d1 < 0) d1 = -d1;
                if (d0 <= delta) w0 += p0;
                if (d1 <= delta) w1 += p1;
            }
        }
        // quad reduction: lanes {4q..4q+3} share rows, hold disjoint bins
#pragma unroll
        for (int o = 1; o <= 2; o <<= 1) {
            t0 += __shfl_xor_sync(0xFFFFFFFFu, t0, o);
            w0 += __shfl_xor_sync(0xFFFFFFFFu, w0, o);
            t1 += __shfl_xor_sync(0xFFFFFFFFu, t1, o);
            w1 += __shfl_xor_sync(0xFFFFFFFFu, w1, o);
        }
        if ((lane & 3) == 0) {
            atomicAdd(&g_acc[2 * row0],           (unsigned long long)llrintf(t0 * FIXS));
            atomicAdd(&g_acc[2 * row0 + 1],       (unsigned long long)llrintf(w0 * FIXS));
            atomicAdd(&g_acc[2 * (row0 + 8)],     (unsigned long long)llrintf(t1 * FIXS));
            atomicAdd(&g_acc[2 * (row0 + 8) + 1], (unsigned long long)llrintf(w1 * FIXS));
        }
    }
}

// ---------------------------------------------------------------------------
// K3: finalize. snr per row + deterministic tree mean -> out[0]. One block.
// ---------------------------------------------------------------------------
__global__ void finalize_kernel(float* __restrict__ out,
                                const int* __restrict__ samp_p,
                                const int* __restrict__ delta_p,
                                const int* __restrict__ fmin_p,
                                const int* __restrict__ fmax_p,
                                int B) {
    __shared__ float red[32];
    const int tid = threadIdx.x, lane = tid & 31, wid = tid >> 5;
    const int samp = *samp_p, delta = *delta_p, fmin = *fmin_p, fmax = *fmax_p;
    const int ngrid = (fmax - fmin) / samp + 1;
    const int nw = 2 * delta / samp + 1;
    const int nu = ngrid - nw;

    float s = 0.f;
    for (int i = tid; i < B; i += 1024) {
        float tot = (float)((long long)g_acc[2 * i])     * (1.0f / FIXS);
        float wan = (float)((long long)g_acc[2 * i + 1]) * (1.0f / FIXS);
        float t1 = wan / (float)nw;
        float t2 = (tot - wan) / (float)nu;
        s += 10.0f * log10f(t1 / t2);
    }
#pragma unroll
    for (int o = 16; o > 0; o >>= 1) s += __shfl_xor_sync(0xFFFFFFFFu, s, o);
    if (lane == 0) red[wid] = s;
    __syncthreads();
    if (wid == 0) {
        s = red[lane];
#pragma unroll
        for (int o = 16; o > 0; o >>= 1) s += __shfl_xor_sync(0xFFFFFFFFu, s, o);
        if (lane == 0) out[0] = -(s / (float)B);
    }
}

// ---------------------------------------------------------------------------
extern "C" void kernel_launch(void* const* d_in, const int* in_sizes, int n_in,
                              void* d_out, int out_size) {
    const float* x     = (const float*)d_in[0];
    const int*   ftrue = (const int*)  d_in[1];
    const int*   fs    = (const int*)  d_in[2];
    const int*   delta = (const int*)  d_in[3];
    const int*   samp  = (const int*)  d_in[4];
    const int*   fmin  = (const int*)  d_in[5];
    const int*   fmax  = (const int*)  d_in[6];

    const int B = in_sizes[1];
    const int T = in_sizes[0] / B;

    prep_kernel<<<2048, 256>>>(x, fs, samp, fmin, fmax, T, B);

    cudaFuncSetAttribute(gemm_mma, cudaFuncAttributeMaxDynamicSharedMemorySize,
                         SMEM_TOTAL);
    gemm_mma<<<dim3(B / BM, 2, 2), 512, SMEM_TOTAL>>>(ftrue, fs, samp, delta,
                                                      fmin, fmax, B, T);

    finalize_kernel<<<1, 1024>>>((float*)d_out, samp, delta, fmin, fmax, B);
}